// round 8
// baseline (speedup 1.0000x reference)
#include <cuda_runtime.h>
#include <cuda_bf16.h>

// out[b,t,v] = sum_d x[b,t,d,v] * w[d] + bias
// x: (2, 512, 8, 32000) fp32 contiguous; w: (8,); b: (1,)
// out: (2, 512, 32000) fp32
//
// HBM-roofline streaming kernel (90%+ of sustained DRAM peak).
// R7: persistent grid-stride — exactly one wave (148 SMs x 7 resident
// blocks), eliminating wave-transition overhead and tail quantization.
// Loads of the next iteration overlap the FMA drain of the current one.

#define DEPTH    8
#define VROW4    8000                    // 32000 floats / 4 per (b,t,d) row
#define TOTAL4   (2L * 512L * VROW4)     // 8,192,000 float4 outputs
#define NBLOCKS  (148 * 7)               // one full wave at 7 blocks/SM
#define NTHREADS 256

__global__ __launch_bounds__(NTHREADS) void ttm_kernel(
    const float4* __restrict__ x,
    const float*  __restrict__ w,
    const float*  __restrict__ bias,
    float4* __restrict__ out)
{
    // weights: tiny, L1/L2-broadcast; registers for the whole kernel
    float wr[DEPTH];
#pragma unroll
    for (int d = 0; d < DEPTH; ++d) wr[d] = __ldg(&w[d]);
    const float bb = __ldg(bias);

    const long stride = (long)NBLOCKS * NTHREADS;            // 265,216

    for (long i = (long)blockIdx.x * NTHREADS + threadIdx.x;
         i < TOTAL4; i += stride)
    {
        int row = (int)(i / VROW4);      // which (b,t) of 1024
        int v4  = (int)(i % VROW4);

        const float4* p = x + (long)row * DEPTH * VROW4 + v4;

        // Front-batch all 8 independent streaming loads (MLP=8)
        float4 t[DEPTH];
#pragma unroll
        for (int d = 0; d < DEPTH; ++d)
            t[d] = __ldcs(p + (long)d * VROW4);   // evict-first: zero reuse

        float4 acc;
        acc.x = bb; acc.y = bb; acc.z = bb; acc.w = bb;

#pragma unroll
        for (int d = 0; d < DEPTH; ++d) {
            acc.x = fmaf(t[d].x, wr[d], acc.x);
            acc.y = fmaf(t[d].y, wr[d], acc.y);
            acc.z = fmaf(t[d].z, wr[d], acc.z);
            acc.w = fmaf(t[d].w, wr[d], acc.w);
        }

        __stcs(&out[i], acc);                     // streaming store
    }
}

extern "C" void kernel_launch(void* const* d_in, const int* in_sizes, int n_in,
                              void* d_out, int out_size)
{
    const float4* x    = (const float4*)d_in[0];
    const float*  w    = (const float*) d_in[1];
    const float*  bias = (const float*) d_in[2];
    float4*       out  = (float4*)      d_out;

    ttm_kernel<<<NBLOCKS, NTHREADS>>>(x, w, bias, out);
}

// round 9
// speedup vs baseline: 1.0517x; 1.0517x over previous
#include <cuda_runtime.h>
#include <cuda_bf16.h>

// out[b,t,v] = sum_d x[b,t,d,v] * w[d] + bias
// x: (2, 512, 8, 32000) fp32 contiguous; w: (8,); b: (1,)
// out: (2, 512, 32000) fp32
//
// Converged HBM-roofline kernel (~90% of sustained DRAM peak, 7.16 TB/s).
// Structure validated across R1-R7:
//  - one thread per float4 of output, 8 front-batched independent float4
//    loads (MLP=8) -> hides DRAM latency, fully coalesced 128B/warp/row
//  - dense one-shot grid (32000 blocks): block rasterization keeps the
//    concurrent address footprint compact -> DRAM page locality
//    (persistent grid-stride measured WORSE: 85.4% DRAM)
//  - exact grid 32000*256 == 8,192,000 outputs: no tail predicate
//  - __ldcs/__stcs streaming hints: measured neutral, kept (zero reuse)

#define DEPTH   8
#define VROW4   8000                    // 32000 floats / 4 per (b,t,d) row
#define TOTAL4  (2L * 512L * VROW4)     // 8,192,000 float4 outputs (exact grid)

__global__ __launch_bounds__(256) void ttm_kernel(
    const float4* __restrict__ x,
    const float*  __restrict__ w,
    const float*  __restrict__ bias,
    float4* __restrict__ out)
{
    long i = (long)blockIdx.x * 256 + threadIdx.x;   // grid is exact: no bounds check

    int row = (int)(i / VROW4);   // which (b,t) of 1024
    int v4  = (int)(i % VROW4);

    // weights: tiny, L1/L2-broadcast; registers for the whole kernel
    float wr[DEPTH];
#pragma unroll
    for (int d = 0; d < DEPTH; ++d) wr[d] = __ldg(&w[d]);
    const float bb = __ldg(bias);

    const float4* p = x + (long)row * DEPTH * VROW4 + v4;

    // Front-batch all 8 independent streaming loads (MLP=8)
    float4 t[DEPTH];
#pragma unroll
    for (int d = 0; d < DEPTH; ++d)
        t[d] = __ldcs(p + (long)d * VROW4);          // evict-first: zero reuse

    float4 acc;
    acc.x = bb; acc.y = bb; acc.z = bb; acc.w = bb;

#pragma unroll
    for (int d = 0; d < DEPTH; ++d) {
        acc.x = fmaf(t[d].x, wr[d], acc.x);
        acc.y = fmaf(t[d].y, wr[d], acc.y);
        acc.z = fmaf(t[d].z, wr[d], acc.z);
        acc.w = fmaf(t[d].w, wr[d], acc.w);
    }

    __stcs(&out[i], acc);                            // streaming store
}

extern "C" void kernel_launch(void* const* d_in, const int* in_sizes, int n_in,
                              void* d_out, int out_size)
{
    const float4* x    = (const float4*)d_in[0];
    const float*  w    = (const float*) d_in[1];
    const float*  bias = (const float*) d_in[2];
    float4*       out  = (float4*)      d_out;

    ttm_kernel<<<32000, 256>>>(x, w, bias, out);
}